// round 2
// baseline (speedup 1.0000x reference)
#include <cuda_runtime.h>

#define N_NODES 100000
#define N_EDGES 1000000
#define DIM 64
#define NB 98  // ceil(N_NODES/1024)

// ---------------- device scratch (no allocations allowed) ----------------
__device__ int   g_is64;
__device__ int   g_deg[N_NODES];
__device__ int   g_rowstart[N_NODES + 1];
__device__ int   g_fill[N_NODES];
__device__ int   g_col[N_EDGES];
__device__ int   g_blocksum[128];
__device__ int   g_blockbase[128];
__device__ float g_mean[N_NODES * DIM];
__device__ float g_p[N_NODES * 2];   // h @ Wl2^T  (to be mean-aggregated)
__device__ float g_q[N_NODES * 2];   // h @ Wr2^T + b2 (local term)

// edge accessor: handles int32 or int64 edge_index transparently
__device__ __forceinline__ int edge_at(const void* ei, int is64, long long idx) {
    if (is64) return (int)((const long long*)ei)[idx];
    return ((const int*)ei)[idx];
}

// ---------------- dtype sniff ----------------
// If int64 with values < 2^31, every odd int32 word is 0. If int32, odd words
// are random node ids (~never all zero across 32 samples).
__global__ void k_sniff(const int* __restrict__ ei32) {
    if (threadIdx.x == 0 && blockIdx.x == 0) {
        int any = 0;
        for (int i = 1; i < 64; i += 2) any |= ei32[i];
        g_is64 = (any == 0) ? 1 : 0;
    }
}

// ---------------- CSR build ----------------
__global__ void k_zero_deg() {
    int i = blockIdx.x * blockDim.x + threadIdx.x;
    if (i < N_NODES) g_deg[i] = 0;
}

__global__ void k_count(const void* __restrict__ ei) {
    int e = blockIdx.x * blockDim.x + threadIdx.x;
    if (e < N_EDGES) {
        int is64 = g_is64;
        int dst = edge_at(ei, is64, (long long)N_EDGES + e);
        if ((unsigned)dst < (unsigned)N_NODES)
            atomicAdd(&g_deg[dst], 1);
    }
}

__global__ void k_blocksum() {
    int b = blockIdx.x, t = threadIdx.x;
    int v = 0;
    for (int i = t; i < 1024; i += 256) {
        int nd = b * 1024 + i;
        if (nd < N_NODES) v += g_deg[nd];
    }
    __shared__ int s[256];
    s[t] = v; __syncthreads();
    for (int o = 128; o > 0; o >>= 1) {
        if (t < o) s[t] += s[t + o];
        __syncthreads();
    }
    if (t == 0) g_blocksum[b] = s[0];
}

__global__ void k_scanbase() {
    __shared__ int s[128];
    int t = threadIdx.x;
    int v = (t < NB) ? g_blocksum[t] : 0;
    s[t] = v; __syncthreads();
    for (int o = 1; o < 128; o <<= 1) {
        int u = (t >= o) ? s[t - o] : 0;
        __syncthreads();
        s[t] += u;
        __syncthreads();
    }
    if (t < NB) g_blockbase[t] = s[t] - v;   // exclusive prefix
    if (t == 0) g_rowstart[N_NODES] = 0;     // real value written below via run
}

__global__ void k_rowstart() {
    __shared__ int ssum[256];
    int b = blockIdx.x, t = threadIdx.x;
    int base_node = b * 1024 + t * 4;
    int v[4]; int tot = 0;
#pragma unroll
    for (int i = 0; i < 4; i++) {
        int nd = base_node + i;
        v[i] = (nd < N_NODES) ? g_deg[nd] : 0;
        tot += v[i];
    }
    ssum[t] = tot; __syncthreads();
    for (int o = 1; o < 256; o <<= 1) {
        int u = (t >= o) ? ssum[t - o] : 0;
        __syncthreads();
        ssum[t] += u;
        __syncthreads();
    }
    int run = g_blockbase[b] + ssum[t] - tot;   // block base + excl within block
#pragma unroll
    for (int i = 0; i < 4; i++) {
        int nd = base_node + i;
        if (nd < N_NODES) {
            g_rowstart[nd] = run;
            g_fill[nd] = run;
            run += v[i];
            if (nd == N_NODES - 1) g_rowstart[N_NODES] = run;
        }
    }
}

__global__ void k_fill(const void* __restrict__ ei) {
    int e = blockIdx.x * blockDim.x + threadIdx.x;
    if (e < N_EDGES) {
        int is64 = g_is64;
        int src = edge_at(ei, is64, e);
        int dst = edge_at(ei, is64, (long long)N_EDGES + e);
        if ((unsigned)dst < (unsigned)N_NODES && (unsigned)src < (unsigned)N_NODES) {
            int pos = atomicAdd(&g_fill[dst], 1);
            if ((unsigned)pos < (unsigned)N_EDGES) g_col[pos] = src;
        }
    }
}

// ---------------- layer 1: mean aggregation (warp per node) ----------------
__global__ void k_gather_mean(const float* __restrict__ x) {
    int w = (blockIdx.x * blockDim.x + threadIdx.x) >> 5;
    if (w >= N_NODES) return;
    int lane = threadIdx.x & 31;
    int s = g_rowstart[w], e = g_rowstart[w + 1];
    float a0 = 0.f, a1 = 0.f;
    for (int j = s; j < e; j++) {
        int src = g_col[j];
        a0 += x[src * 64 + lane];
        a1 += x[src * 64 + 32 + lane];
    }
    float inv = 1.f / (float)max(e - s, 1);
    g_mean[w * 64 + lane]      = a0 * inv;
    g_mean[w * 64 + 32 + lane] = a1 * inv;
}

// ---------------- layer 1 node GEMM + fused layer-2 projections ----------------
// h = relu(mean @ Wl1^T + x @ Wr1^T + b1);  p = h @ Wl2^T;  q = h @ Wr2^T + b2
__global__ __launch_bounds__(128) void k_layer1(
    const float* __restrict__ x,
    const float* __restrict__ Wl1, const float* __restrict__ Wr1,
    const float* __restrict__ b1,
    const float* __restrict__ Wl2, const float* __restrict__ Wr2,
    const float* __restrict__ b2)
{
    __shared__ __align__(16) float sWl[64 * 64];
    __shared__ __align__(16) float sWr[64 * 64];
    __shared__ float sL2[128], sR2[128], sB1[64];

    int t = threadIdx.x;
    for (int i = t; i < 64 * 64; i += 128) { sWl[i] = Wl1[i]; sWr[i] = Wr1[i]; }
    if (t < 128) { sL2[t] = Wl2[t]; sR2[t] = Wr2[t]; }
    if (t < 64)  sB1[t] = b1[t];
    __syncthreads();

    int n = blockIdx.x * 128 + t;
    if (n >= N_NODES) return;

    float acc[64];
#pragma unroll
    for (int j = 0; j < 64; j++) acc[j] = 0.f;

    const float4* m4 = (const float4*)(g_mean + (size_t)n * 64);
    const float4* x4 = (const float4*)(x + (size_t)n * 64);
    const float4* wl4 = (const float4*)sWl;
    const float4* wr4 = (const float4*)sWr;

    for (int kk = 0; kk < 16; kk++) {   // k rolled, j unrolled: accs stay in regs
        float4 m = m4[kk];
        float4 xv = x4[kk];
#pragma unroll
        for (int j = 0; j < 64; j++) {
            float4 wl = wl4[j * 16 + kk];
            float4 wr = wr4[j * 16 + kk];
            acc[j] += m.x * wl.x + m.y * wl.y + m.z * wl.z + m.w * wl.w
                    + xv.x * wr.x + xv.y * wr.y + xv.z * wr.z + xv.w * wr.w;
        }
    }

    float p0 = 0.f, p1 = 0.f, q0 = 0.f, q1 = 0.f;
#pragma unroll
    for (int j = 0; j < 64; j++) {
        float hj = fmaxf(acc[j] + sB1[j], 0.f);
        p0 += hj * sL2[j];       p1 += hj * sL2[64 + j];
        q0 += hj * sR2[j];       q1 += hj * sR2[64 + j];
    }
    g_p[n * 2]     = p0;
    g_p[n * 2 + 1] = p1;
    g_q[n * 2]     = q0 + b2[0];
    g_q[n * 2 + 1] = q1 + b2[1];
}

// ---------------- layer 2: mean-aggregate p (2 floats/edge) + local q ----------------
__global__ void k_layer2_out(float* __restrict__ out) {
    int w = (blockIdx.x * blockDim.x + threadIdx.x) >> 5;
    if (w >= N_NODES) return;
    int lane = threadIdx.x & 31;
    int s = g_rowstart[w], e = g_rowstart[w + 1];
    float a0 = 0.f, a1 = 0.f;
    for (int j = s + lane; j < e; j += 32) {
        int src = g_col[j];
        float2 pv = *(const float2*)(g_p + src * 2);
        a0 += pv.x; a1 += pv.y;
    }
#pragma unroll
    for (int o = 16; o > 0; o >>= 1) {
        a0 += __shfl_xor_sync(0xFFFFFFFFu, a0, o);
        a1 += __shfl_xor_sync(0xFFFFFFFFu, a1, o);
    }
    if (lane == 0) {
        float inv = 1.f / (float)max(e - s, 1);
        out[w * 2]     = a0 * inv + g_q[w * 2];
        out[w * 2 + 1] = a1 * inv + g_q[w * 2 + 1];
    }
}

// ---------------- launch ----------------
extern "C" void kernel_launch(void* const* d_in, const int* in_sizes, int n_in,
                              void* d_out, int out_size)
{
    const float* x   = (const float*)d_in[0];
    const void*  ei  = d_in[1];                 // int32 or int64, sniffed on device
    const float* Wl1 = (const float*)d_in[2];
    const float* Wr1 = (const float*)d_in[3];
    const float* b1  = (const float*)d_in[4];
    const float* Wl2 = (const float*)d_in[5];
    const float* Wr2 = (const float*)d_in[6];
    const float* b2  = (const float*)d_in[7];
    float* out = (float*)d_out;

    k_sniff<<<1, 32>>>((const int*)ei);
    k_zero_deg<<<(N_NODES + 255) / 256, 256>>>();
    k_count<<<(N_EDGES + 255) / 256, 256>>>(ei);
    k_blocksum<<<NB, 256>>>();
    k_scanbase<<<1, 128>>>();
    k_rowstart<<<NB, 256>>>();
    k_fill<<<(N_EDGES + 255) / 256, 256>>>(ei);

    int warps_grid = (N_NODES * 32 + 255) / 256;
    k_gather_mean<<<warps_grid, 256>>>(x);
    k_layer1<<<(N_NODES + 127) / 128, 128>>>(x, Wl1, Wr1, b1, Wl2, Wr2, b2);
    k_layer2_out<<<warps_grid, 256>>>(out);
}

// round 3
// speedup vs baseline: 1.0250x; 1.0250x over previous
#include <cuda_runtime.h>

#define N_NODES 100000
#define N_EDGES 1000000
#define NB 98  // ceil(N_NODES/1024)

// ---------------- device scratch (no allocations allowed) ----------------
__device__ int   g_is64;
__device__ int   g_deg[N_NODES];
__device__ int   g_rowstart[N_NODES + 1];
__device__ int   g_fill[N_NODES];
__device__ int   g_col[N_EDGES];
__device__ int   g_blocksum[128];
__device__ int   g_blockbase[128];
__device__ float g_mean[N_NODES * 64];
__device__ float g_p[N_NODES * 2];   // h @ Wl2^T  (to be mean-aggregated)
__device__ float g_q[N_NODES * 2];   // h @ Wr2^T + b2 (local term)

__device__ __forceinline__ int edge_at(const void* ei, int is64, long long idx) {
    if (is64) return (int)((const long long*)ei)[idx];
    return ((const int*)ei)[idx];
}

// ---------------- init: zero degrees + dtype sniff ----------------
__global__ void k_init(const int* __restrict__ ei32) {
    int i = blockIdx.x * blockDim.x + threadIdx.x;
    if (i < N_NODES) g_deg[i] = 0;
    if (i == 0) {
        // int64 nonneg < 2^31 => every odd int32 word is 0
        int any = 0;
        for (int s = 1; s < 64; s += 2) any |= ei32[s];
        g_is64 = (any == 0) ? 1 : 0;
    }
}

// ---------------- CSR build ----------------
__global__ void k_count(const void* __restrict__ ei) {
    int e = blockIdx.x * blockDim.x + threadIdx.x;
    if (e < N_EDGES) {
        int dst = edge_at(ei, g_is64, (long long)N_EDGES + e);
        if ((unsigned)dst < (unsigned)N_NODES)
            atomicAdd(&g_deg[dst], 1);
    }
}

__global__ void k_blocksum() {
    int b = blockIdx.x, t = threadIdx.x;
    int v = 0;
    for (int i = t; i < 1024; i += 256) {
        int nd = b * 1024 + i;
        if (nd < N_NODES) v += g_deg[nd];
    }
    __shared__ int s[256];
    s[t] = v; __syncthreads();
    for (int o = 128; o > 0; o >>= 1) {
        if (t < o) s[t] += s[t + o];
        __syncthreads();
    }
    if (t == 0) g_blocksum[b] = s[0];
}

__global__ void k_scanbase() {
    __shared__ int s[128];
    int t = threadIdx.x;
    int v = (t < NB) ? g_blocksum[t] : 0;
    s[t] = v; __syncthreads();
    for (int o = 1; o < 128; o <<= 1) {
        int u = (t >= o) ? s[t - o] : 0;
        __syncthreads();
        s[t] += u;
        __syncthreads();
    }
    if (t < NB) g_blockbase[t] = s[t] - v;   // exclusive prefix
    if (t == 0) g_rowstart[N_NODES] = 0;     // real value set in k_rowstart
}

__global__ void k_rowstart() {
    __shared__ int ssum[256];
    int b = blockIdx.x, t = threadIdx.x;
    int base_node = b * 1024 + t * 4;
    int v[4]; int tot = 0;
#pragma unroll
    for (int i = 0; i < 4; i++) {
        int nd = base_node + i;
        v[i] = (nd < N_NODES) ? g_deg[nd] : 0;
        tot += v[i];
    }
    ssum[t] = tot; __syncthreads();
    for (int o = 1; o < 256; o <<= 1) {
        int u = (t >= o) ? ssum[t - o] : 0;
        __syncthreads();
        ssum[t] += u;
        __syncthreads();
    }
    int run = g_blockbase[b] + ssum[t] - tot;
#pragma unroll
    for (int i = 0; i < 4; i++) {
        int nd = base_node + i;
        if (nd < N_NODES) {
            g_rowstart[nd] = run;
            g_fill[nd] = run;
            run += v[i];
            if (nd == N_NODES - 1) g_rowstart[N_NODES] = run;
        }
    }
}

__global__ void k_fill(const void* __restrict__ ei) {
    int e = blockIdx.x * blockDim.x + threadIdx.x;
    if (e < N_EDGES) {
        int is64 = g_is64;
        int src = edge_at(ei, is64, e);
        int dst = edge_at(ei, is64, (long long)N_EDGES + e);
        if ((unsigned)dst < (unsigned)N_NODES && (unsigned)src < (unsigned)N_NODES) {
            int pos = atomicAdd(&g_fill[dst], 1);
            if ((unsigned)pos < (unsigned)N_EDGES) g_col[pos] = src;
        }
    }
}

// ---------------- layer 1: mean aggregation (warp per node, MLP-unrolled) ----------------
__global__ void k_gather_mean(const float* __restrict__ x) {
    int w = (blockIdx.x * blockDim.x + threadIdx.x) >> 5;
    if (w >= N_NODES) return;
    int lane = threadIdx.x & 31;
    int s = g_rowstart[w], e = g_rowstart[w + 1];
    float a0 = 0.f, a1 = 0.f, a2 = 0.f, a3 = 0.f;
    float b0 = 0.f, b1 = 0.f, b2 = 0.f, b3 = 0.f;
    int j = s;
    int nn = e - ((e - s) & 3);
    for (; j < nn; j += 4) {
        int c0 = g_col[j], c1 = g_col[j + 1], c2 = g_col[j + 2], c3 = g_col[j + 3];
        a0 += x[c0 * 64 + lane];       b0 += x[c0 * 64 + 32 + lane];
        a1 += x[c1 * 64 + lane];       b1 += x[c1 * 64 + 32 + lane];
        a2 += x[c2 * 64 + lane];       b2 += x[c2 * 64 + 32 + lane];
        a3 += x[c3 * 64 + lane];       b3 += x[c3 * 64 + 32 + lane];
    }
    for (; j < e; j++) {
        int c = g_col[j];
        a0 += x[c * 64 + lane];        b0 += x[c * 64 + 32 + lane];
    }
    float inv = 1.f / (float)max(e - s, 1);
    g_mean[w * 64 + lane]      = ((a0 + a1) + (a2 + a3)) * inv;
    g_mean[w * 64 + 32 + lane] = ((b0 + b1) + (b2 + b3)) * inv;
}

// ---------------- layer 1 GEMM (outer-product tiled, packed f32x2) ----------------
// h = relu([mean||x] @ [Wl1||Wr1]^T + b1);  p = h@Wl2^T;  q = h@Wr2^T + b2
// Block: 256 threads, tile = 128 nodes x 64 outs, K = 128.
// Thread (tn = t/8, tj = t%8): 4 nodes (tn*4..+3) x 8 outs (tj*8..+7) = 16 f32x2 accs.
#define KC 16
#define WPAD 68   // 272B row: 16B-aligned, shifts banks per k
#define APAD 132  // 528B row: 16B-aligned

__device__ __forceinline__ unsigned long long pack2(float v) {
    unsigned long long r;
    asm("mov.b64 %0, {%1, %1};" : "=l"(r) : "f"(v));
    return r;
}
__device__ __forceinline__ void fma2(unsigned long long& acc,
                                     unsigned long long a, unsigned long long w) {
    asm("fma.rn.f32x2 %0, %1, %2, %0;" : "+l"(acc) : "l"(a), "l"(w));
}

__global__ __launch_bounds__(256) void k_layer1(
    const float* __restrict__ x,
    const float* __restrict__ Wl1, const float* __restrict__ Wr1,
    const float* __restrict__ b1,
    const float* __restrict__ Wl2, const float* __restrict__ Wr2,
    const float* __restrict__ b2)
{
    __shared__ __align__(16) float sWt[128][WPAD];  // [k][j] transposed
    __shared__ __align__(16) float sAs[KC][APAD];   // [k][n] transposed chunk
    __shared__ float sL2[128], sR2[128], sB1[64];

    int t = threadIdx.x;
    // weights transposed into smem: Wl1/Wr1 are [j][k] row-major
    for (int i = t; i < 64 * 64; i += 256) {
        int j = i >> 6, k = i & 63;
        float wl = Wl1[i], wr = Wr1[i];
        sWt[k][j]      = wl;
        sWt[k + 64][j] = wr;
    }
    if (t < 128) { sL2[t] = Wl2[t]; sR2[t] = Wr2[t]; }
    if (t < 64)  sB1[t] = b1[t];

    int tn = t >> 3;          // 0..31 : node group
    int tj = t & 7;           // 0..7  : out group
    int nodeBase = blockIdx.x * 128;

    unsigned long long acc[4][4];
#pragma unroll
    for (int i = 0; i < 4; i++)
#pragma unroll
        for (int jp = 0; jp < 4; jp++) acc[i][jp] = 0ull;

    // stage thread mapping: row r = t/2 (node), half = t%2 selects 8 floats
    int r  = t >> 1;
    int kq = (t & 1) * 2;     // float4 index within 16-float chunk
    int nL = nodeBase + r; if (nL >= N_NODES) nL = N_NODES - 1;

    for (int ch = 0; ch < 8; ch++) {  // 8 chunks of K=16
        __syncthreads();
        {
            const float* src = (ch < 4) ? (g_mean + (size_t)nL * 64 + ch * 16)
                                        : (x      + (size_t)nL * 64 + (ch - 4) * 16);
            const float4* s4 = (const float4*)src;
#pragma unroll
            for (int q = 0; q < 2; q++) {
                float4 v = s4[kq + q];
                int kk = (kq + q) * 4;
                sAs[kk][r] = v.x; sAs[kk + 1][r] = v.y;
                sAs[kk + 2][r] = v.z; sAs[kk + 3][r] = v.w;
            }
        }
        __syncthreads();
        int kbase = ch * KC;
#pragma unroll
        for (int k = 0; k < KC; k++) {
            float4 a4 = *(const float4*)&sAs[k][tn * 4];
            unsigned long long a2[4];
            a2[0] = pack2(a4.x); a2[1] = pack2(a4.y);
            a2[2] = pack2(a4.z); a2[3] = pack2(a4.w);
            const float* wrow = &sWt[kbase + k][tj * 8];
            unsigned long long w2[4];
            { // two 16B loads -> 4 packed (j, j+1) pairs
                float4 w0 = *(const float4*)(wrow);
                float4 w1 = *(const float4*)(wrow + 4);
                w2[0] = *(unsigned long long*)&w0.x;
                w2[1] = *(unsigned long long*)&w0.z;
                w2[2] = *(unsigned long long*)&w1.x;
                w2[3] = *(unsigned long long*)&w1.z;
            }
#pragma unroll
            for (int i = 0; i < 4; i++)
#pragma unroll
                for (int jp = 0; jp < 4; jp++)
                    fma2(acc[i][jp], a2[i], w2[jp]);
        }
    }

    // epilogue: relu + bias, project to p (Wl2) and q (Wr2), reduce over tj lanes
    float bq0 = b2[0], bq1 = b2[1];
#pragma unroll
    for (int i = 0; i < 4; i++) {
        float p0 = 0.f, p1 = 0.f, q0 = 0.f, q1 = 0.f;
#pragma unroll
        for (int jp = 0; jp < 4; jp++) {
            float lo, hi;
            asm("mov.b64 {%0, %1}, %2;" : "=f"(lo), "=f"(hi) : "l"(acc[i][jp]));
            int j = tj * 8 + jp * 2;
            float h0 = fmaxf(lo + sB1[j], 0.f);
            float h1 = fmaxf(hi + sB1[j + 1], 0.f);
            p0 += h0 * sL2[j]      + h1 * sL2[j + 1];
            p1 += h0 * sL2[64 + j] + h1 * sL2[64 + j + 1];
            q0 += h0 * sR2[j]      + h1 * sR2[j + 1];
            q1 += h0 * sR2[64 + j] + h1 * sR2[64 + j + 1];
        }
#pragma unroll
        for (int o = 4; o > 0; o >>= 1) {
            p0 += __shfl_xor_sync(0xFFFFFFFFu, p0, o);
            p1 += __shfl_xor_sync(0xFFFFFFFFu, p1, o);
            q0 += __shfl_xor_sync(0xFFFFFFFFu, q0, o);
            q1 += __shfl_xor_sync(0xFFFFFFFFu, q1, o);
        }
        if (tj == 0) {
            int n = nodeBase + tn * 4 + i;
            if (n < N_NODES) {
                g_p[n * 2]     = p0;
                g_p[n * 2 + 1] = p1;
                g_q[n * 2]     = q0 + bq0;
                g_q[n * 2 + 1] = q1 + bq1;
            }
        }
    }
}

// ---------------- layer 2: mean-aggregate p (2 floats/edge) + local q ----------------
__global__ void k_layer2_out(float* __restrict__ out) {
    int w = (blockIdx.x * blockDim.x + threadIdx.x) >> 5;
    if (w >= N_NODES) return;
    int lane = threadIdx.x & 31;
    int s = g_rowstart[w], e = g_rowstart[w + 1];
    float a0 = 0.f, a1 = 0.f;
    for (int j = s + lane; j < e; j += 32) {
        int src = g_col[j];
        float2 pv = *(const float2*)(g_p + src * 2);
        a0 += pv.x; a1 += pv.y;
    }
#pragma unroll
    for (int o = 16; o > 0; o >>= 1) {
        a0 += __shfl_xor_sync(0xFFFFFFFFu, a0, o);
        a1 += __shfl_xor_sync(0xFFFFFFFFu, a1, o);
    }
    if (lane == 0) {
        float inv = 1.f / (float)max(e - s, 1);
        out[w * 2]     = a0 * inv + g_q[w * 2];
        out[w * 2 + 1] = a1 * inv + g_q[w * 2 + 1];
    }
}

// ---------------- launch ----------------
extern "C" void kernel_launch(void* const* d_in, const int* in_sizes, int n_in,
                              void* d_out, int out_size)
{
    const float* x   = (const float*)d_in[0];
    const void*  ei  = d_in[1];                 // int32 or int64, sniffed on device
    const float* Wl1 = (const float*)d_in[2];
    const float* Wr1 = (const float*)d_in[3];
    const float* b1  = (const float*)d_in[4];
    const float* Wl2 = (const float*)d_in[5];
    const float* Wr2 = (const float*)d_in[6];
    const float* b2  = (const float*)d_in[7];
    float* out = (float*)d_out;

    k_init<<<(N_NODES + 255) / 256, 256>>>((const int*)ei);
    k_count<<<(N_EDGES + 255) / 256, 256>>>(ei);
    k_blocksum<<<NB, 256>>>();
    k_scanbase<<<1, 128>>>();
    k_rowstart<<<NB, 256>>>();
    k_fill<<<(N_EDGES + 255) / 256, 256>>>(ei);

    int warps_grid = (N_NODES * 32 + 255) / 256;
    k_gather_mean<<<warps_grid, 256>>>(x);
    k_layer1<<<(N_NODES + 127) / 128, 128 * 2>>>(x, Wl1, Wr1, b1, Wl2, Wr2, b2);
    k_layer2_out<<<warps_grid, 256>>>(out);
}